// round 9
// baseline (speedup 1.0000x reference)
#include <cuda_runtime.h>
#include <math.h>

#define Bsz 4
#define Ssz 2048
#define DVs 1024
#define Hs  16
#define Dhd 64
#define Tsz 64
#define DTs 768

#define LOG2E 1.4426950408889634f
#define QSCALE (0.125f * LOG2E)

// Scratch (allocation-free).
// g_q/g_k: [B,H,S,Dh] tf32 bits, d pair-permuted within groups of 8; q pre-scaled.
// g_v:     [B,H,Dh,S] tf32 bits, S pair-permuted within groups of 8.
// g_xt:    X tf32 bits, k pair-permuted within groups of 8.
// g_wt:    W tf32 bits, interleaved k-pair layout: [pair][n][2],
//          pair p holds (orig k = p, orig k = p+4) within each group of 8.
__device__ float g_q[Bsz * Hs * Ssz * Dhd];
__device__ float g_k[Bsz * Hs * Ssz * Dhd];
__device__ float g_v[Bsz * Hs * Ssz * Dhd];
__device__ float g_gate[2][Bsz * DVs];
__device__ float g_pool[Bsz][DTs];
__device__ float g_xt[Bsz * Ssz * DVs];
__device__ float g_wt[3][DVs * DVs];

// ---------------------------------------------------------------------------
// helpers
// ---------------------------------------------------------------------------
__device__ __forceinline__ unsigned f2tf32(float x) {
    unsigned u;
    asm("cvt.rna.tf32.f32 %0, %1;" : "=r"(u) : "f"(x));
    return u;
}

__device__ __forceinline__ void mma_tf32(float* c, const unsigned* a, const unsigned* b) {
    asm volatile(
        "mma.sync.aligned.m16n8k8.row.col.f32.tf32.tf32.f32 "
        "{%0,%1,%2,%3}, {%4,%5,%6,%7}, {%8,%9}, {%0,%1,%2,%3};"
        : "+f"(c[0]), "+f"(c[1]), "+f"(c[2]), "+f"(c[3])
        : "r"(a[0]), "r"(a[1]), "r"(a[2]), "r"(a[3]), "r"(b[0]), "r"(b[1]));
}

__device__ __forceinline__ unsigned smem_u32(const void* p) {
    return (unsigned)__cvta_generic_to_shared(p);
}
__device__ __forceinline__ void cp16(unsigned dst, const void* src) {
    asm volatile("cp.async.cg.shared.global [%0], [%1], 16;" :: "r"(dst), "l"(src));
}
#define CP_COMMIT() asm volatile("cp.async.commit_group;")
#define CP_WAIT(n)  asm volatile("cp.async.wait_group %0;" :: "n"(n))

// ---------------------------------------------------------------------------
// Kernel 0a: convert X -> tf32 bits, k pair-permuted within groups of 8.
// ---------------------------------------------------------------------------
__global__ void cvtx_kernel(const float* __restrict__ X) {
    size_t g = (size_t)blockIdx.x * blockDim.x + threadIdx.x;
    const float4* in = (const float4*)(X + g * 8);
    float4 i0 = in[0], i1 = in[1];
    uint4 o0, o1;
    o0.x = f2tf32(i0.x); o0.y = f2tf32(i1.x); o0.z = f2tf32(i0.y); o0.w = f2tf32(i1.y);
    o1.x = f2tf32(i0.z); o1.y = f2tf32(i1.z); o1.z = f2tf32(i0.w); o1.w = f2tf32(i1.w);
    uint4* out = (uint4*)(g_xt + g * 8);
    out[0] = o0;
    out[1] = o1;
}

// ---------------------------------------------------------------------------
// Kernel 0b: convert W -> tf32 bits, interleaved k-pair layout.
// stored row s = perm(k); pair P = s>>1, sub = s&1; word = P*2*DVs + n*2 + sub.
// ---------------------------------------------------------------------------
__global__ void cvtw_kernel(const float* __restrict__ Wq,
                            const float* __restrict__ Wk,
                            const float* __restrict__ Wv) {
    size_t idx = (size_t)blockIdx.x * blockDim.x + threadIdx.x;
    int sel = (int)(idx / (DVs * DVs / 4));
    size_t rem = idx % (DVs * DVs / 4);
    int k = (int)(rem / (DVs / 4));
    int c4 = (int)(rem % (DVs / 4)) * 4;
    const float* W = sel == 0 ? Wq : (sel == 1 ? Wk : Wv);
    int j = k & 7;
    int s = (k & ~7) | (j < 4 ? 2 * j : 2 * j - 7);
    int P = s >> 1, sub = s & 1;
    float4 v = *(const float4*)&W[(size_t)k * DVs + c4];
    float* base = &g_wt[sel][(size_t)P * (2 * DVs) + (size_t)c4 * 2 + sub];
    base[0] = __uint_as_float(f2tf32(v.x));
    base[2] = __uint_as_float(f2tf32(v.y));
    base[4] = __uint_as_float(f2tf32(v.z));
    base[6] = __uint_as_float(f2tf32(v.w));
}

// ---------------------------------------------------------------------------
// Kernel 1a: masked-mean pool. grid(B), 256 threads.
// ---------------------------------------------------------------------------
__global__ void pool_kernel(const float* __restrict__ txt,
                            const float* __restrict__ tmask) {
    int b = blockIdx.x, tid = threadIdx.x;
    __shared__ float tm[Tsz];
    if (tid < Tsz) tm[tid] = tmask[b * Tsz + tid];
    __syncthreads();
    float ms = 0.f;
    #pragma unroll 8
    for (int t = 0; t < Tsz; t++) ms += tm[t];
    float inv = 1.f / ms;
    for (int d = tid; d < DTs; d += 256) {
        float acc = 0.f;
        #pragma unroll 8
        for (int t = 0; t < Tsz; t++)
            acc += txt[(b * Tsz + t) * DTs + d] * tm[t];
        g_pool[b][d] = acc * inv;
    }
}

// ---------------------------------------------------------------------------
// Kernel 1b: gates GEMV, warp-per-output. grid(DV/8, 2, B), 256 threads.
// ---------------------------------------------------------------------------
__global__ void gates_kernel(const float* __restrict__ Wdq, const float* __restrict__ bdq,
                             const float* __restrict__ Wdk, const float* __restrict__ bdk) {
    int which = blockIdx.y, b = blockIdx.z;
    const float* W    = which ? Wdk : Wdq;
    const float* bias = which ? bdk : bdq;
    int w = threadIdx.x >> 5, lane = threadIdx.x & 31;
    int n = blockIdx.x * 8 + w;

    float dot = 0.f;
    #pragma unroll 6
    for (int d = lane; d < DTs; d += 32)
        dot += g_pool[b][d] * W[d * DVs + n];
    #pragma unroll
    for (int off = 16; off; off >>= 1)
        dot += __shfl_xor_sync(0xffffffffu, dot, off);
    if (lane == 0) {
        float x = dot + bias[n];
        g_gate[which][b * DVs + n] = 1.f + 1.f / (1.f + __expf(-x));
    }
}

// ---------------------------------------------------------------------------
// Kernel 2: QKV projection, tf32 mma, 3-stage cp.async, BK=32.
// A-frags LDS.64 (permuted X); B-frags LDS.64 (interleaved-pair W).
// Stage: Xs[128][36] + Ws[16 pairs][264] = 8832 words.
// ---------------------------------------------------------------------------
#define QKV_XW 36
#define QKV_WW 264
#define QKV_STAGE (128 * QKV_XW + 16 * QKV_WW)

__global__ void __launch_bounds__(256, 2) qkv_kernel(
        const float* __restrict__ bq,
        const float* __restrict__ bk,
        const float* __restrict__ bv) {
    extern __shared__ float smq[];
    int sel = blockIdx.z;
    const float* W    = g_wt[sel];
    const float* bias = sel == 0 ? bq : (sel == 1 ? bk : bv);
    float* dst        = sel == 0 ? g_q : (sel == 1 ? g_k : g_v);

    int tid = threadIdx.x;
    int w = tid >> 5, lane = tid & 31;
    int tg = lane & 3, gid = lane >> 2;
    int tg2 = 2 * tg;
    int warp_m = (w & 1) * 64, warp_n = (w >> 1) * 32;
    int m0 = blockIdx.y * 128, n0 = blockIdx.x * 128;

    // loader chunk mapping: 4 X chunks + 4 W chunks per thread per stage
    int xr[4], xq[4], wp[4], wn[4];
    #pragma unroll
    for (int i = 0; i < 4; i++) {
        int c = tid + i * 256;
        xr[i] = c >> 3;  xq[i] = (c & 7) * 4;
        wp[i] = c >> 6;  wn[i] = (c & 63) * 4;
    }

    const float* Xb = g_xt + (size_t)m0 * DVs;
    const float* Wb = W + (size_t)n0 * 2;

    float acc[4][4][4] = {};

    #pragma unroll
    for (int p = 0; p < 2; p++) {
        float* Xs = smq + p * QKV_STAGE;
        float* Ws = Xs + 128 * QKV_XW;
        int k0 = p * 32, kp0 = p * 16;
        #pragma unroll
        for (int i = 0; i < 4; i++) {
            cp16(smem_u32(Xs + xr[i] * QKV_XW + xq[i]),
                 Xb + (size_t)xr[i] * DVs + k0 + xq[i]);
            cp16(smem_u32(Ws + wp[i] * QKV_WW + wn[i]),
                 Wb + (size_t)(kp0 + wp[i]) * (2 * DVs) + wn[i]);
        }
        CP_COMMIT();
    }

    int st = 0, st_ld = 2;
    for (int it = 0; it < 32; it++) {
        CP_WAIT(1);
        __syncthreads();

        if (it + 2 < 32) {
            float* Xs = smq + st_ld * QKV_STAGE;
            float* Ws = Xs + 128 * QKV_XW;
            int k0 = (it + 2) * 32, kp0 = (it + 2) * 16;
            #pragma unroll
            for (int i = 0; i < 4; i++) {
                cp16(smem_u32(Xs + xr[i] * QKV_XW + xq[i]),
                     Xb + (size_t)xr[i] * DVs + k0 + xq[i]);
                cp16(smem_u32(Ws + wp[i] * QKV_WW + wn[i]),
                     Wb + (size_t)(kp0 + wp[i]) * (2 * DVs) + wn[i]);
            }
        }
        CP_COMMIT();

        const unsigned* Xs = (const unsigned*)(smq + st * QKV_STAGE);
        const unsigned* Ws = Xs + 128 * QKV_XW;

        #pragma unroll
        for (int ks = 0; ks < 4; ks++) {
            int kb = ks * 8;
            unsigned a[4][4];
            #pragma unroll
            for (int mi = 0; mi < 4; mi++) {
                int r = warp_m + mi * 16 + gid;
                uint2 u0 = *(const uint2*)&Xs[r * QKV_XW + kb + tg2];
                uint2 u1 = *(const uint2*)&Xs[(r + 8) * QKV_XW + kb + tg2];
                a[mi][0] = u0.x; a[mi][1] = u1.x; a[mi][2] = u0.y; a[mi][3] = u1.y;
            }
            #pragma unroll
            for (int nj = 0; nj < 4; nj++) {
                uint2 bb = *(const uint2*)&Ws[(ks * 4 + tg) * QKV_WW +
                                              (warp_n + nj * 8 + gid) * 2];
                unsigned bfr[2] = {bb.x, bb.y};
                #pragma unroll
                for (int mi = 0; mi < 4; mi++)
                    mma_tf32(acc[mi][nj], a[mi], bfr);
            }
        }
        st = (st == 2) ? 0 : st + 1;
        st_ld = (st_ld == 2) ? 0 : st_ld + 1;
    }

    if (sel < 2) {
        // q/k: [B,H,S,Dh], d pair-permuted; q pre-scaled by 0.125*log2e
        float qs = (sel == 0) ? QSCALE : 1.f;
        const float* gate = g_gate[sel];
        int p0 = tg2;
        int sc = (p0 < 4) ? 2 * p0 : 2 * p0 - 7;
        #pragma unroll
        for (int nj = 0; nj < 4; nj++) {
            int colb = n0 + warp_n + nj * 8;
            int col = colb + p0;
            int h = colb >> 6, ddb = colb & 63;
            float b0 = bias[col], b1 = bias[col + 1];
            #pragma unroll
            for (int mi = 0; mi < 4; mi++) {
                int r0 = m0 + warp_m + mi * 16 + gid;
                int bb = r0 >> 11, s0 = r0 & 2047;
                float g0 = gate[bb * DVs + col];
                float g1 = gate[bb * DVs + col + 1];
                float v00 = (acc[mi][nj][0] + b0) * g0 * qs;
                float v01 = (acc[mi][nj][1] + b1) * g1 * qs;
                float v10 = (acc[mi][nj][2] + b0) * g0 * qs;
                float v11 = (acc[mi][nj][3] + b1) * g1 * qs;
                size_t base = ((size_t)bb * Hs + h) * Ssz;
                float* d0p = &dst[(base + s0) * Dhd + ddb];
                float* d1p = &dst[(base + s0 + 8) * Dhd + ddb];
                d0p[sc]     = __uint_as_float(f2tf32(v00));
                d0p[sc + 2] = __uint_as_float(f2tf32(v01));
                d1p[sc]     = __uint_as_float(f2tf32(v10));
                d1p[sc + 2] = __uint_as_float(f2tf32(v11));
            }
        }
    } else {
        // v: transposed [B,H,Dh,S], s pair-permuted within groups of 8
        int sp = (gid < 4) ? 2 * gid : 2 * gid - 7;
        #pragma unroll
        for (int nj = 0; nj < 4; nj++) {
            int col = n0 + warp_n + nj * 8 + tg2;
            int h = col >> 6, dd = col & 63;
            float b0 = bias[col], b1 = bias[col + 1];
            #pragma unroll
            for (int mi = 0; mi < 4; mi++) {
                int r0 = m0 + warp_m + mi * 16 + gid;
                int bb = r0 >> 11, s0 = r0 & 2047;
                int sb = s0 - gid;
                size_t row0 = ((size_t)bb * Hs + h) * Dhd + dd;
                dst[row0 * Ssz + sb + sp] =
                    __uint_as_float(f2tf32(acc[mi][nj][0] + b0));
                dst[(row0 + 1) * Ssz + sb + sp] =
                    __uint_as_float(f2tf32(acc[mi][nj][1] + b1));
                dst[row0 * Ssz + sb + 8 + sp] =
                    __uint_as_float(f2tf32(acc[mi][nj][2] + b0));
                dst[(row0 + 1) * Ssz + sb + 8 + sp] =
                    __uint_as_float(f2tf32(acc[mi][nj][3] + b1));
            }
        }
    }
}

// ---------------------------------------------------------------------------
// Kernel 3: flash attention. Q/K d-permuted, V transposed + kv-permuted,
// K rows ALSO kv-permuted in smem so S C-frag cols = PV A-frag k-order:
// P conversion is shuffle-free. All mma fragment loads LDS.64.
// ---------------------------------------------------------------------------
#define ATTN_QS   (128 * 72)
#define ATTN_KST  (64 * 72)
#define ATTN_VST  (64 * 72)

__global__ void __launch_bounds__(256, 2) attn_kernel(
        const float* __restrict__ amask, float* __restrict__ out) {
    extern __shared__ float sma[];
    unsigned* Qs = (unsigned*)sma;                 // [128 q][72] permuted d
    float* Kbuf = sma + ATTN_QS;                   // [2][64 kv(perm)][72] permuted d
    float* Vbuf = sma + ATTN_QS + 2 * ATTN_KST;    // [2][64 d][72] permuted kv

    int q0 = blockIdx.x * 128;
    int h = blockIdx.y, b = blockIdx.z;
    int tid = threadIdx.x;
    int w = tid >> 5, lane = tid & 31;
    int tg = lane & 3, gid = lane >> 2;
    int qr = w * 16;
    int tg2 = 2 * tg;

    const float* qbase = g_q + ((size_t)(b * Hs + h)) * Ssz * Dhd;
    const float* kbase = g_k + ((size_t)(b * Hs + h)) * Ssz * Dhd;
    const float* vbase = g_v + ((size_t)(b * Hs + h)) * Dhd * Ssz;

    // loader chunk mapping; K source rows kv-pair-permuted (dest row cr ->
    // src row (cr>>1)+4*(cr&1) within each group of 8)
    int cr[4], cq[4], kcr[4];
    #pragma unroll
    for (int i = 0; i < 4; i++) {
        int c = tid + i * 256;
        cr[i] = c >> 4;
        cq[i] = (c & 15) * 4;
        int sl = cr[i] & 7;
        kcr[i] = (cr[i] & ~7) | ((sl >> 1) | ((sl & 1) << 2));
    }

    #pragma unroll
    for (int it = 0; it < 8; it++) {
        int idx = it * 256 + tid;
        int r = idx >> 4, c4 = (idx & 15) * 4;
        *(uint4*)&Qs[r * 72 + c4] = *(const uint4*)&qbase[(size_t)(q0 + r) * Dhd + c4];
    }

    #pragma unroll
    for (int p = 0; p < 2; p++) {
        float* Kr = Kbuf + p * ATTN_KST;
        float* Vr = Vbuf + p * ATTN_VST;
        int kr0 = p * 64;
        #pragma unroll
        for (int i = 0; i < 4; i++) {
            cp16(smem_u32(Kr + cr[i] * 72 + cq[i]),
                 kbase + (size_t)(kr0 + kcr[i]) * Dhd + cq[i]);
            cp16(smem_u32(Vr + cr[i] * 72 + cq[i]),
                 vbase + (size_t)cr[i] * Ssz + kr0 + cq[i]);
        }
        CP_COMMIT();
    }

    float o[8][4] = {};
    float m0 = -1e30f, m1 = -1e30f, l0 = 0.f, l1 = 0.f;

    for (int kt = 0; kt < Ssz / 64; kt++) {
        int kr0 = kt * 64;
        int buf = kt & 1;
        const unsigned* Kr = (const unsigned*)(Kbuf + buf * ATTN_KST);
        const unsigned* Vr = (const unsigned*)(Vbuf + buf * ATTN_VST);

        CP_WAIT(1);
        __syncthreads();

        // S = Q K^T  (C cols are kv-permuted: thread cols = orig kv tg, tg+4)
        float s[8][4] = {};
        #pragma unroll
        for (int ks = 0; ks < 8; ks++) {
            int kb = ks * 8;
            uint2 a01 = *(const uint2*)&Qs[(qr + gid) * 72 + kb + tg2];
            uint2 a23 = *(const uint2*)&Qs[(qr + gid + 8) * 72 + kb + tg2];
            unsigned a[4] = {a01.x, a23.x, a01.y, a23.y};
            #pragma unroll
            for (int j = 0; j < 8; j++) {
                uint2 bb = *(const uint2*)&Kr[(j * 8 + gid) * 72 + kb + tg2];
                unsigned bfr[2] = {bb.x, bb.y};
                mma_tf32(s[j], a, bfr);
            }
        }

        // mask (x log2e; cols tg, tg+4) + online softmax (base-2)
        float mx0 = -1e30f, mx1 = -1e30f;
        #pragma unroll
        for (int j = 0; j < 8; j++) {
            float mk0 = amask[b * Ssz + kr0 + j * 8 + tg] * LOG2E;
            float mk1 = amask[b * Ssz + kr0 + j * 8 + tg + 4] * LOG2E;
            s[j][0] += mk0; s[j][1] += mk1;
            s[j][2] += mk0; s[j][3] += mk1;
            mx0 = fmaxf(mx0, fmaxf(s[j][0], s[j][1]));
            mx1 = fmaxf(mx1, fmaxf(s[j][2], s[j][3]));
        }
        #pragma unroll
        for (int off = 1; off <= 2; off <<= 1) {
            mx0 = fmaxf(mx0, __shfl_xor_sync(0xffffffffu, mx0, off));
            mx1 = fmaxf(mx1, __shfl_xor_sync(0xffffffffu, mx1, off));
        }
        float mn0 = fmaxf(m0, mx0), mn1 = fmaxf(m1, mx1);
        float al0 = exp2f(m0 - mn0), al1 = exp2f(m1 - mn1);
        m0 = mn0; m1 = mn1;

        float rs0 = 0.f, rs1 = 0.f;
        #pragma unroll
        for (int j = 0; j < 8; j++) {
            s[j][0] = exp2f(s[j][0] - mn0);
            s[j][1] = exp2f(s[j][1] - mn0);
            s[j][2] = exp2f(s[j][2] - mn1);
            s[j][3] = exp2f(s[j][3] - mn1);
            rs0 += s[j][0] + s[j][1];
            rs1 += s[j][2] + s[j][3];
        }
        #pragma unroll
        for (int off = 1; off <= 2; off <<= 1) {
            rs0 += __shfl_xor_sync(0xffffffffu, rs0, off);
            rs1 += __shfl_xor_sync(0xffffffffu, rs1, off);
        }
        l0 = l0 * al0 + rs0;
        l1 = l1 * al1 + rs1;

        #pragma unroll
        for (int dj = 0; dj < 8; dj++) {
            o[dj][0] *= al0; o[dj][1] *= al0;
            o[dj][2] *= al1; o[dj][3] *= al1;
        }

        // O += P V : shuffle-free A-frag (C cols already in A-frag k-order)
        #pragma unroll
        for (int j = 0; j < 8; j++) {
            unsigned pa[4];
            pa[0] = f2tf32(s[j][0]);
            pa[1] = f2tf32(s[j][2]);
            pa[2] = f2tf32(s[j][1]);
            pa[3] = f2tf32(s[j][3]);
            #pragma unroll
            for (int dj = 0; dj < 8; dj++) {
                uint2 vv = *(const uint2*)&Vr[(dj * 8 + gid) * 72 + j * 8 + tg2];
                unsigned bfr[2] = {vv.x, vv.y};
                mma_tf32(o[dj], pa, bfr);
            }
        }

        __syncthreads();
        if (kt + 2 < Ssz / 64) {
            float* Kw = Kbuf + buf * ATTN_KST;
            float* Vw = Vbuf + buf * ATTN_VST;
            int kn0 = (kt + 2) * 64;
            #pragma unroll
            for (int i = 0; i < 4; i++) {
                cp16(smem_u32(Kw + cr[i] * 72 + cq[i]),
                     kbase + (size_t)(kn0 + kcr[i]) * Dhd + cq[i]);
                cp16(smem_u32(Vw + cr[i] * 72 + cq[i]),
                     vbase + (size_t)cr[i] * Ssz + kn0 + cq[i]);
            }
        }
        CP_COMMIT();
    }

    float inv0 = 1.f / l0, inv1 = 1.f / l1;
    int r0 = q0 + qr + gid, r1 = r0 + 8;
    #pragma unroll
    for (int dj = 0; dj < 8; dj++) {
        int col = h * Dhd + dj * 8 + tg2;
        float2 o0 = {o[dj][0] * inv0, o[dj][1] * inv0};
        float2 o1 = {o[dj][2] * inv1, o[dj][3] * inv1};
        *(float2*)&out[((size_t)b * Ssz + r0) * DVs + col] = o0;
        *(float2*)&out[((size_t)b * Ssz + r1) * DVs + col] = o1;
    }
}

// ---------------------------------------------------------------------------
extern "C" void kernel_launch(void* const* d_in, const int* in_sizes, int n_in,
                              void* d_out, int out_size) {
    const float* X     = (const float*)d_in[0];
    const float* amask = (const float*)d_in[1];
    const float* txt   = (const float*)d_in[2];
    const float* tmask = (const float*)d_in[3];
    const float* Wq  = (const float*)d_in[4];
    const float* bq  = (const float*)d_in[5];
    const float* Wk  = (const float*)d_in[6];
    const float* bk  = (const float*)d_in[7];
    const float* Wv  = (const float*)d_in[8];
    const float* bv  = (const float*)d_in[9];
    const float* Wdq = (const float*)d_in[10];
    const float* bdq = (const float*)d_in[11];
    const float* Wdk = (const float*)d_in[12];
    const float* bdk = (const float*)d_in[13];
    float* out = (float*)d_out;

    pool_kernel<<<Bsz, 256>>>(txt, tmask);
    gates_kernel<<<dim3(DVs / 8, 2, Bsz), 256>>>(Wdq, bdq, Wdk, bdk);

    cvtx_kernel<<<(Bsz * Ssz * DVs / 8) / 256, 256>>>(X);
    cvtw_kernel<<<(3 * DVs * DVs / 4) / 256, 256>>>(Wq, Wk, Wv);

    int smq = 3 * QKV_STAGE * (int)sizeof(float);  // 105984 B
    cudaFuncSetAttribute(qkv_kernel, cudaFuncAttributeMaxDynamicSharedMemorySize, smq);
    qkv_kernel<<<dim3(DVs / 128, (Bsz * Ssz) / 128, 3), 256, smq>>>(bq, bk, bv);

    int sma = (ATTN_QS + 2 * ATTN_KST + 2 * ATTN_VST) * (int)sizeof(float);  // 110592 B
    cudaFuncSetAttribute(attn_kernel, cudaFuncAttributeMaxDynamicSharedMemorySize, sma);
    attn_kernel<<<dim3(Ssz / 128, Hs, Bsz), 256, sma>>>(amask, out);
}